// round 9
// baseline (speedup 1.0000x reference)
#include <cuda_runtime.h>
#include <cuda_bf16.h>
#include <cstdint>

// Problem dims (fixed): N=262144 rows, d_in=1024, d_hid=256, 128 bags.
#define NROWS_MAX 262144
#define DIN 1024
#define DHID 256
#define NEG_INF_F (__int_as_float(0xff800000))

__device__ float          g_h[(size_t)NROWS_MAX * DHID];
__device__ float          g_scores[NROWS_MAX];
__device__ float          g_psum[2048 * 256];
__device__ float          g_psumsq[2048 * 256];
__device__ float          g_bn_a[DHID];
__device__ float          g_bn_c[DHID];
__device__ long long      g_off[1025];
__device__ unsigned short g_Bhi[(size_t)DHID * DIN];
__device__ unsigned short g_Blo[(size_t)DHID * DIN];

// ---------------- helpers ----------------
__device__ __forceinline__ uint32_t smem_u32(const void* p) {
    uint32_t a;
    asm("{ .reg .u64 t; cvta.to.shared.u64 t, %1; cvt.u32.u64 %0, t; }" : "=r"(a) : "l"(p));
    return a;
}
__device__ __forceinline__ uint32_t prm_hi(float a, float b) {
    return __byte_perm(__float_as_uint(a), __float_as_uint(b), 0x7632);
}
__device__ __forceinline__ uint32_t pack2(float first, float second) {
    uint32_t r;
    asm("cvt.rn.bf16x2.f32 %0, %1, %2;" : "=r"(r) : "f"(second), "f"(first));
    return r;
}
__device__ __forceinline__ float trunc_hi(float x) {
    return __uint_as_float(__float_as_uint(x) & 0xFFFF0000u);
}
__device__ __forceinline__ void ldm4(uint32_t* r, uint32_t addr) {
    asm volatile("ldmatrix.sync.aligned.m8n8.x4.shared.b16 {%0,%1,%2,%3}, [%4];"
                 : "=r"(r[0]), "=r"(r[1]), "=r"(r[2]), "=r"(r[3]) : "r"(addr));
}
__device__ __forceinline__ void mma16816(float* c, const uint32_t* a, uint32_t b0, uint32_t b1) {
    asm volatile(
        "mma.sync.aligned.m16n8k16.row.col.f32.bf16.bf16.f32 "
        "{%0,%1,%2,%3}, {%4,%5,%6,%7}, {%8,%9}, {%0,%1,%2,%3};"
        : "+f"(c[0]), "+f"(c[1]), "+f"(c[2]), "+f"(c[3])
        : "r"(a[0]), "r"(a[1]), "r"(a[2]), "r"(a[3]), "r"(b0), "r"(b1));
}
#define CP_ASYNC16(dst, src) \
    asm volatile("cp.async.ca.shared.global [%0], [%1], 16;" :: "r"(dst), "l"(src) : "memory")
#define CP_COMMIT()  asm volatile("cp.async.commit_group;" ::: "memory")
#define CP_WAIT0()   asm volatile("cp.async.wait_group 0;" ::: "memory")

// ---------------------------------------------------------------------------
// Kernel 0: W1 split to bf16 hi/lo, K-major
// ---------------------------------------------------------------------------
__global__ __launch_bounds__(256)
void convert_w1_kernel(const float* __restrict__ W1)
{
    const int n = blockIdx.x;
    const int t = threadIdx.x;
    #pragma unroll
    for (int i = 0; i < DIN / 256; ++i) {
        int k = t + 256 * i;
        float x = W1[(size_t)k * DHID + n];
        uint32_t xb = __float_as_uint(x);
        float hi = __uint_as_float(xb & 0xFFFF0000u);
        float lo = x - hi;
        g_Bhi[(size_t)n * DIN + k] = (unsigned short)(xb >> 16);
        __nv_bfloat16 lb = __float2bfloat16_rn(lo);
        g_Blo[(size_t)n * DIN + k] = *(unsigned short*)&lb;
    }
}

// ---------------------------------------------------------------------------
// Kernel 1: mma.sync split-bf16 GEMM, full-N CTA tile 128x256, 512 threads.
// 16 warps = 4(m) x 4(n), warp tile 32x64. KC=32 double-buffered.
// Smem/buffer: A 16KB (128 rows x 128B: hi units 0-3, lo 4-7, XOR swizzle),
//              B 32KB (256 rows x 128B, same layout). 2 buffers = 96KB.
// ---------------------------------------------------------------------------
__global__ __launch_bounds__(512, 1)
void gemm_mma_kernel(const float* __restrict__ A, const float* __restrict__ b1, int nrows)
{
    extern __shared__ __align__(16) char sm[];
    __shared__ float sbias[DHID];

    const int tid  = threadIdx.x;
    const int wid  = tid >> 5;
    const int lane = tid & 31;
    const int row0 = blockIdx.x * 128;

    const uint32_t smbase = smem_u32(sm);
    const int BUF = 49152;   // per-buffer: A 16KB @ +0, B 32KB @ +16384

    if (tid < 256) sbias[tid] = b1[tid];

    // ---- A staging map: thread -> (row = tid>>2, k-unit = tid&3, 8 floats) ----
    const int arow = tid >> 2;
    const int au   = tid & 3;                 // hi 16B unit index; lo = au+4
    const float* abase = A + (size_t)(row0 + arow) * DIN + au * 8;
    const uint32_t a_hi_of = (uint32_t)arow * 128 + (((au    ) ^ (arow & 7)) << 4);
    const uint32_t a_lo_of = (uint32_t)arow * 128 + (((au + 4) ^ (arow & 7)) << 4);

    // ---- B staging map: thread -> (row = tid>>1, units {2h,2h+1} hi + lo) ----
    const int bn = tid >> 1;
    const int bh = tid & 1;
    const int u0 = 2 * bh, u1 = 2 * bh + 1;
    const unsigned short* bhp = g_Bhi + (size_t)bn * DIN;
    const unsigned short* blp = g_Blo + (size_t)bn * DIN;
    const uint32_t b_row = 16384u + (uint32_t)bn * 128;
    const uint32_t b_h0 = b_row + (((u0    ) ^ (bn & 7)) << 4);
    const uint32_t b_h1 = b_row + (((u1    ) ^ (bn & 7)) << 4);
    const uint32_t b_l0 = b_row + (((u0 + 4) ^ (bn & 7)) << 4);
    const uint32_t b_l1 = b_row + (((u1 + 4) ^ (bn & 7)) << 4);

    // ---- stage chunk 0 ----
    {
        CP_ASYNC16(smbase + b_h0, bhp + u0 * 8);
        CP_ASYNC16(smbase + b_h1, bhp + u1 * 8);
        CP_ASYNC16(smbase + b_l0, blp + u0 * 8);
        CP_ASYNC16(smbase + b_l1, blp + u1 * 8);
        CP_COMMIT();
        float4 f0 = *(const float4*)(abase);
        float4 f1 = *(const float4*)(abase + 4);
        *(uint4*)(sm + a_hi_of) = make_uint4(prm_hi(f0.x, f0.y), prm_hi(f0.z, f0.w),
                                             prm_hi(f1.x, f1.y), prm_hi(f1.z, f1.w));
        *(uint4*)(sm + a_lo_of) = make_uint4(
            pack2(f0.x - trunc_hi(f0.x), f0.y - trunc_hi(f0.y)),
            pack2(f0.z - trunc_hi(f0.z), f0.w - trunc_hi(f0.w)),
            pack2(f1.x - trunc_hi(f1.x), f1.y - trunc_hi(f1.y)),
            pack2(f1.z - trunc_hi(f1.z), f1.w - trunc_hi(f1.w)));
        CP_WAIT0();
    }
    __syncthreads();

    // ---- warp compute mapping: 4m x 4n ----
    const int m0w  = (wid >> 2) * 32;
    const int n0w  = (wid & 3) * 64;
    const int lr   = lane & 15;
    const int lsel = (lane >> 4) & 1;

    float acc[2][8][4];
    #pragma unroll
    for (int mt = 0; mt < 2; ++mt)
        #pragma unroll
        for (int nt = 0; nt < 8; ++nt)
            #pragma unroll
            for (int q = 0; q < 4; ++q) acc[mt][nt][q] = 0.f;

    const int NKC = DIN / 32;
    for (int kc = 0; kc < NKC; ++kc) {
        const uint32_t cur = (uint32_t)(kc & 1) * BUF;
        const bool pf = (kc + 1) < NKC;
        const uint32_t nxt = (uint32_t)((kc + 1) & 1) * BUF;

        float4 f0, f1;
        if (pf) {
            const int ko = (kc + 1) * 32;
            CP_ASYNC16(smbase + nxt + b_h0, bhp + ko + u0 * 8);
            CP_ASYNC16(smbase + nxt + b_h1, bhp + ko + u1 * 8);
            CP_ASYNC16(smbase + nxt + b_l0, blp + ko + u0 * 8);
            CP_ASYNC16(smbase + nxt + b_l1, blp + ko + u1 * 8);
            CP_COMMIT();
            f0 = *(const float4*)(abase + ko);
            f1 = *(const float4*)(abase + ko + 4);
        }

        #pragma unroll
        for (int ks = 0; ks < 2; ++ks) {
            uint32_t ah[2][4], al[2][4];
            const uint32_t ubh = (uint32_t)(2 * ks + lsel);
            #pragma unroll
            for (int mt = 0; mt < 2; ++mt) {
                int r = m0w + mt * 16 + lr;
                uint32_t base = smbase + cur + r * 128;
                ldm4(ah[mt], base + (((ubh    ) ^ (r & 7)) << 4));
                ldm4(al[mt], base + (((ubh + 4) ^ (r & 7)) << 4));
            }
            #pragma unroll
            for (int ph = 0; ph < 2; ++ph) {
                uint32_t bhf[2][4], blf[2][4];
                #pragma unroll
                for (int q = 0; q < 2; ++q) {
                    int rn = n0w + (2 * ph + q) * 16 + lr;
                    uint32_t base = smbase + cur + 16384 + rn * 128;
                    ldm4(bhf[q], base + (((ubh    ) ^ (rn & 7)) << 4));
                    ldm4(blf[q], base + (((ubh + 4) ^ (rn & 7)) << 4));
                }
                #pragma unroll
                for (int q = 0; q < 2; ++q)
                    #pragma unroll
                    for (int mt = 0; mt < 2; ++mt) {
                        int p = 2 * ph + q;
                        mma16816(acc[mt][2 * p],     ah[mt], bhf[q][0], bhf[q][2]);
                        mma16816(acc[mt][2 * p + 1], ah[mt], bhf[q][1], bhf[q][3]);
                    }
                #pragma unroll
                for (int q = 0; q < 2; ++q)
                    #pragma unroll
                    for (int mt = 0; mt < 2; ++mt) {
                        int p = 2 * ph + q;
                        mma16816(acc[mt][2 * p],     ah[mt], blf[q][0], blf[q][2]);
                        mma16816(acc[mt][2 * p + 1], ah[mt], blf[q][1], blf[q][3]);
                    }
                #pragma unroll
                for (int q = 0; q < 2; ++q)
                    #pragma unroll
                    for (int mt = 0; mt < 2; ++mt) {
                        int p = 2 * ph + q;
                        mma16816(acc[mt][2 * p],     al[mt], bhf[q][0], bhf[q][2]);
                        mma16816(acc[mt][2 * p + 1], al[mt], bhf[q][1], bhf[q][3]);
                    }
            }
        }

        if (pf) {
            *(uint4*)(sm + nxt + a_hi_of) = make_uint4(prm_hi(f0.x, f0.y), prm_hi(f0.z, f0.w),
                                                       prm_hi(f1.x, f1.y), prm_hi(f1.z, f1.w));
            *(uint4*)(sm + nxt + a_lo_of) = make_uint4(
                pack2(f0.x - trunc_hi(f0.x), f0.y - trunc_hi(f0.y)),
                pack2(f0.z - trunc_hi(f0.z), f0.w - trunc_hi(f0.w)),
                pack2(f1.x - trunc_hi(f1.x), f1.y - trunc_hi(f1.y)),
                pack2(f1.z - trunc_hi(f1.z), f1.w - trunc_hi(f1.w)));
            CP_WAIT0();
        }
        __syncthreads();
    }

    // ---- epilogue: bias add, write g_h, fused column sum/sumsq ----
    const int erow = lane >> 2;
    const int ecol = (lane & 3) * 2;
    float* ss = (float*)sm;                 // [16 warps][8 nt][4 grp][2] = 1024 floats
    float* qq = (float*)(sm + 4096);
    #pragma unroll
    for (int nt = 0; nt < 8; ++nt) {
        int gc = n0w + nt * 8 + ecol;
        float bx = sbias[gc], by = sbias[gc + 1];
        float sx = 0.f, sy = 0.f, qx = 0.f, qy = 0.f;
        #pragma unroll
        for (int mt = 0; mt < 2; ++mt) {
            int gr0 = row0 + m0w + mt * 16 + erow;
            float2 v0 = make_float2(acc[mt][nt][0] + bx, acc[mt][nt][1] + by);
            float2 v1 = make_float2(acc[mt][nt][2] + bx, acc[mt][nt][3] + by);
            *(float2*)&g_h[(size_t)gr0 * DHID + gc]       = v0;
            *(float2*)&g_h[(size_t)(gr0 + 8) * DHID + gc] = v1;
            sx += v0.x + v1.x;  sy += v0.y + v1.y;
            qx = fmaf(v0.x, v0.x, fmaf(v1.x, v1.x, qx));
            qy = fmaf(v0.y, v0.y, fmaf(v1.y, v1.y, qy));
        }
        #pragma unroll
        for (int o = 4; o < 32; o <<= 1) {
            sx += __shfl_xor_sync(0xffffffffu, sx, o);
            sy += __shfl_xor_sync(0xffffffffu, sy, o);
            qx += __shfl_xor_sync(0xffffffffu, qx, o);
            qy += __shfl_xor_sync(0xffffffffu, qy, o);
        }
        if (lane < 4) {
            int idx = ((wid * 8 + nt) * 4 + lane) * 2;
            ss[idx] = sx;  ss[idx + 1] = sy;
            qq[idx] = qx;  qq[idx + 1] = qy;
        }
    }
    __syncthreads();
    if (tid < 256) {
        const int lc = tid;                 // global column
        const int nw = lc >> 6;             // which n-warp column group
        const int within = lc & 63;
        const int nt  = within >> 3;
        const int grp = (within & 7) >> 1;
        const int xy  = within & 1;
        float s = 0.f, q = 0.f;
        #pragma unroll
        for (int mw = 0; mw < 4; ++mw) {
            int wd = mw * 4 + nw;
            int idx = ((wd * 8 + nt) * 4 + grp) * 2 + xy;
            s += ss[idx];
            q += qq[idx];
        }
        g_psum[(size_t)blockIdx.x * 256 + lc]   = s;
        g_psumsq[(size_t)blockIdx.x * 256 + lc] = q;
    }
}

// ---------------------------------------------------------------------------
// Kernel 3: finalize BN coefficients (256 blocks, tree reduce over 2048 CTAs)
// ---------------------------------------------------------------------------
__global__ __launch_bounds__(256)
void stats_final_kernel(const float* __restrict__ gamma,
                        const float* __restrict__ beta, int nrows)
{
    __shared__ float rs[256], rq[256];
    const int c   = blockIdx.x;
    const int tid = threadIdx.x;
    float s = 0.f, q = 0.f;
    for (int y = tid; y < 2048; y += 256) {
        s += g_psum[(size_t)y * 256 + c];
        q += g_psumsq[(size_t)y * 256 + c];
    }
    rs[tid] = s; rq[tid] = q;
    __syncthreads();
    #pragma unroll
    for (int o = 128; o; o >>= 1) {
        if (tid < o) { rs[tid] += rs[tid + o]; rq[tid] += rq[tid + o]; }
        __syncthreads();
    }
    if (tid == 0) {
        float inv_n = 1.0f / (float)nrows;
        float mean  = rs[0] * inv_n;
        float var   = fmaf(-mean, mean, rq[0] * inv_n);
        float rstd  = rsqrtf(var + 1e-5f);
        float a     = gamma[c] * rstd;
        g_bn_a[c] = a;
        g_bn_c[c] = fmaf(-mean, a, beta[c]);
    }
}

// Kernel 4: scores (warp per row)
__global__ __launch_bounds__(256)
void scores_kernel(const float* __restrict__ W2, const float* __restrict__ b2,
                   int nrows)
{
    __shared__ float sa[DHID], sc[DHID], sw[DHID];
    const int tid = threadIdx.x;
    sa[tid] = g_bn_a[tid];
    sc[tid] = g_bn_c[tid];
    sw[tid] = W2[tid];
    __syncthreads();

    const int warp = tid >> 5;
    const int lane = tid & 31;
    const int row  = blockIdx.x * 8 + warp;
    if (row >= nrows) return;

    const float* hr = g_h + (size_t)row * DHID;
    float acc = 0.f;
    #pragma unroll
    for (int part = 0; part < 2; ++part) {
        int c0 = part * 128 + lane * 4;
        float4 v = *(const float4*)(hr + c0);
        acc += fmaxf(fmaf(sa[c0 + 0], v.x, sc[c0 + 0]), 0.f) * sw[c0 + 0];
        acc += fmaxf(fmaf(sa[c0 + 1], v.y, sc[c0 + 1]), 0.f) * sw[c0 + 1];
        acc += fmaxf(fmaf(sa[c0 + 2], v.z, sc[c0 + 2]), 0.f) * sw[c0 + 2];
        acc += fmaxf(fmaf(sa[c0 + 3], v.w, sc[c0 + 3]), 0.f) * sw[c0 + 3];
    }
    #pragma unroll
    for (int o = 16; o; o >>= 1) acc += __shfl_xor_sync(0xffffffffu, acc, o);
    if (lane == 0) g_scores[row] = acc + b2[0];
}

// Kernel 5: bag offsets
__global__ void offsets_kernel(const int* __restrict__ bag_sizes, int n_bags)
{
    if (threadIdx.x == 0 && blockIdx.x == 0) {
        long long a = 0;
        g_off[0] = 0;
        for (int b = 0; b < n_bags; ++b) { a += (long long)bag_sizes[b]; g_off[b + 1] = a; }
    }
}

// Kernel 6: per-bag stable softmax
__global__ __launch_bounds__(256)
void bag_softmax_kernel(float* __restrict__ out)
{
    __shared__ float red[256];
    const int b   = blockIdx.x;
    const int tid = threadIdx.x;
    const long long s = g_off[b];
    const long long e = g_off[b + 1];

    float m = NEG_INF_F;
    for (long long i = s + tid; i < e; i += 256) m = fmaxf(m, g_scores[i]);
    red[tid] = m;
    __syncthreads();
    #pragma unroll
    for (int o = 128; o; o >>= 1) {
        if (tid < o) red[tid] = fmaxf(red[tid], red[tid + o]);
        __syncthreads();
    }
    const float M = red[0];
    __syncthreads();

    float z = 0.f;
    for (long long i = s + tid; i < e; i += 256) {
        float ev = expf(g_scores[i] - M);
        out[i] = ev;
        z += ev;
    }
    red[tid] = z;
    __syncthreads();
    #pragma unroll
    for (int o = 128; o; o >>= 1) {
        if (tid < o) red[tid] += red[tid + o];
        __syncthreads();
    }
    const float inv = 1.0f / red[0];
    for (long long i = s + tid; i < e; i += 256) out[i] *= inv;
}

// ---------------------------------------------------------------------------
extern "C" void kernel_launch(void* const* d_in, const int* in_sizes, int n_in,
                              void* d_out, int out_size)
{
    const float* features  = (const float*)d_in[0];
    const int*   bag_sizes = (const int*)d_in[1];
    const float* W1        = (const float*)d_in[2];
    const float* b1        = (const float*)d_in[3];
    const float* gamma     = (const float*)d_in[4];
    const float* beta      = (const float*)d_in[5];
    const float* W2        = (const float*)d_in[6];
    const float* b2        = (const float*)d_in[7];
    float*       out       = (float*)d_out;

    const int n      = out_size;        // 262144
    const int n_bags = in_sizes[1];     // 128

    const int GEMM_SMEM = 98304;        // 2 x (16KB A + 32KB B)
    cudaFuncSetAttribute(gemm_mma_kernel,
                         cudaFuncAttributeMaxDynamicSharedMemorySize, GEMM_SMEM);

    convert_w1_kernel<<<DHID, 256>>>(W1);
    gemm_mma_kernel<<<n / 128, 512, GEMM_SMEM>>>(features, b1, n);
    stats_final_kernel<<<DHID, 256>>>(gamma, beta, n);
    scores_kernel<<<(n + 7) / 8, 256>>>(W2, b2, n);
    offsets_kernel<<<1, 1>>>(bag_sizes, n_bags);
    bag_softmax_kernel<<<n_bags, 256>>>(out);
}

// round 10
// speedup vs baseline: 1.2463x; 1.2463x over previous
#include <cuda_runtime.h>
#include <cuda_fp16.h>
#include <cstdint>

// Problem dims (fixed): N=262144 rows, d_in=1024, d_hid=256, 128 bags.
#define NROWS_MAX 262144
#define DIN 1024
#define DHID 256
#define NEG_INF_F (__int_as_float(0xff800000))

__device__ float          g_h[(size_t)NROWS_MAX * DHID];
__device__ float          g_scores[NROWS_MAX];
__device__ float          g_psum[4096 * 128];
__device__ float          g_psumsq[4096 * 128];
__device__ float          g_bn_a[DHID];
__device__ float          g_bn_c[DHID];
__device__ long long      g_off[1025];
__device__ unsigned short g_Bhi[(size_t)DHID * DIN];   // W1^T hi fp16 [256][1024]
__device__ unsigned short g_Blo[(size_t)DHID * DIN];   // W1^T lo fp16

// ---------------- helpers ----------------
__device__ __forceinline__ uint32_t smem_u32(const void* p) {
    uint32_t a;
    asm("{ .reg .u64 t; cvta.to.shared.u64 t, %1; cvt.u32.u64 %0, t; }" : "=r"(a) : "l"(p));
    return a;
}
// fp16x2 pack, memory order: first, second (mirrors verified bf16 pack order)
__device__ __forceinline__ uint32_t pack2h(float first, float second) {
    uint32_t r;
    asm("cvt.rn.f16x2.f32 %0, %1, %2;" : "=r"(r) : "f"(second), "f"(first));
    return r;
}
__device__ __forceinline__ void ldm4(uint32_t* r, uint32_t addr) {
    asm volatile("ldmatrix.sync.aligned.m8n8.x4.shared.b16 {%0,%1,%2,%3}, [%4];"
                 : "=r"(r[0]), "=r"(r[1]), "=r"(r[2]), "=r"(r[3]) : "r"(addr));
}
__device__ __forceinline__ void mma16816h(float* c, const uint32_t* a, uint32_t b0, uint32_t b1) {
    asm volatile(
        "mma.sync.aligned.m16n8k16.row.col.f32.f16.f16.f32 "
        "{%0,%1,%2,%3}, {%4,%5,%6,%7}, {%8,%9}, {%0,%1,%2,%3};"
        : "+f"(c[0]), "+f"(c[1]), "+f"(c[2]), "+f"(c[3])
        : "r"(a[0]), "r"(a[1]), "r"(a[2]), "r"(a[3]), "r"(b0), "r"(b1));
}
#define CP_ASYNC16(dst, src) \
    asm volatile("cp.async.ca.shared.global [%0], [%1], 16;" :: "r"(dst), "l"(src) : "memory")
#define CP_COMMIT()  asm volatile("cp.async.commit_group;" ::: "memory")
#define CP_WAIT0()   asm volatile("cp.async.wait_group 0;" ::: "memory")

// ---------------------------------------------------------------------------
// Kernel 0: W1 [1024][256] fp32 -> fp16 hi/lo, K-major [256][1024]
// ---------------------------------------------------------------------------
__global__ __launch_bounds__(256)
void convert_w1_kernel(const float* __restrict__ W1)
{
    const int n = blockIdx.x;
    const int t = threadIdx.x;
    #pragma unroll
    for (int i = 0; i < DIN / 256; ++i) {
        int k = t + 256 * i;
        float x = W1[(size_t)k * DHID + n];
        __half hh = __float2half_rn(x);
        float lo = x - __half2float(hh);
        __half hl = __float2half_rn(lo);
        g_Bhi[(size_t)n * DIN + k] = *(unsigned short*)&hh;
        g_Blo[(size_t)n * DIN + k] = *(unsigned short*)&hl;
    }
}

// ---------------------------------------------------------------------------
// Kernel 1: mma.sync 2-term fp16 GEMM  h = A1*(Bhi+Blo) + b1, fused col stats.
// CTA 128m x 128n (grid (2, N/128)), 256 threads, 8 warps 4m x 2n, warp 32x64.
// KC=32 double-buffered. Per-buffer: A 8KB (2 rows packed per 128B block,
// sub-row XOR swizzle) + B 16KB (row n: 128B = hi 64B | lo 64B, XOR swizzle).
// Per ks: A 2 ldm4 (hi only), B 8 ldm4; 2 sweeps x 16 independent MMAs.
// ---------------------------------------------------------------------------
__global__ __launch_bounds__(256, 2)
void gemm_mma_kernel(const float* __restrict__ A, const float* __restrict__ b1, int nrows)
{
    extern __shared__ __align__(16) char sm[];
    __shared__ float sbias[128];

    const int tid  = threadIdx.x;
    const int wid  = tid >> 5;
    const int lane = tid & 31;
    const int n0   = blockIdx.x * 128;
    const int row0 = blockIdx.y * 128;

    const uint32_t smbase = smem_u32(sm);
    const int BUF = 24576;   // per-buffer: A 8KB @ +0, B 16KB @ +8192

    if (tid < 128) sbias[tid] = b1[n0 + tid];

    // ---- A staging map: row = tid>>1 (two threads per row), k-units (tid&1)*2,+1
    const int arow = tid >> 1;
    const int asub = arow & 1;               // sub-row within 128B block
    const int ablk = arow >> 1;              // 128B block index (0..63)
    const int ku0  = (tid & 1) * 2;          // logical 16B unit within row (0..3)
    const float* abase = A + (size_t)(row0 + arow) * DIN + (tid & 1) * 16;
    const uint32_t a_st0 = (uint32_t)ablk * 128 + (((asub * 4 + ku0    ) ^ (ablk & 7)) << 4);
    const uint32_t a_st1 = (uint32_t)ablk * 128 + (((asub * 4 + ku0 + 1) ^ (ablk & 7)) << 4);

    // ---- B staging map: row = tid>>1, half = tid&1 -> hi units 2h,2h+1; lo 4+2h,4+2h+1
    const int bn = tid >> 1;
    const int bh = tid & 1;
    const unsigned short* bhp = g_Bhi + (size_t)(n0 + bn) * DIN + bh * 16;
    const unsigned short* blp = g_Blo + (size_t)(n0 + bn) * DIN + bh * 16;
    const uint32_t b_row = 8192u + (uint32_t)bn * 128;
    const uint32_t b_h0 = b_row + (((2 * bh    ) ^ (bn & 7)) << 4);
    const uint32_t b_h1 = b_row + (((2 * bh + 1) ^ (bn & 7)) << 4);
    const uint32_t b_l0 = b_row + (((4 + 2 * bh    ) ^ (bn & 7)) << 4);
    const uint32_t b_l1 = b_row + (((4 + 2 * bh + 1) ^ (bn & 7)) << 4);

    // ---- stage chunk 0 ----
    {
        CP_ASYNC16(smbase + b_h0, bhp);
        CP_ASYNC16(smbase + b_h1, bhp + 8);
        CP_ASYNC16(smbase + b_l0, blp);
        CP_ASYNC16(smbase + b_l1, blp + 8);
        CP_COMMIT();
        float4 f0 = *(const float4*)(abase);
        float4 f1 = *(const float4*)(abase + 4);
        float4 f2 = *(const float4*)(abase + 8);
        float4 f3 = *(const float4*)(abase + 12);
        *(uint4*)(sm + a_st0) = make_uint4(pack2h(f0.x, f0.y), pack2h(f0.z, f0.w),
                                           pack2h(f1.x, f1.y), pack2h(f1.z, f1.w));
        *(uint4*)(sm + a_st1) = make_uint4(pack2h(f2.x, f2.y), pack2h(f2.z, f2.w),
                                           pack2h(f3.x, f3.y), pack2h(f3.z, f3.w));
        CP_WAIT0();
    }
    __syncthreads();

    const int m0w  = (wid & 3) * 32;
    const int n0w  = (wid >> 2) * 64;
    const int lr   = lane & 15;
    const int lsel = (lane >> 4) & 1;

    float acc[2][8][4];
    #pragma unroll
    for (int mt = 0; mt < 2; ++mt)
        #pragma unroll
        for (int nt = 0; nt < 8; ++nt)
            #pragma unroll
            for (int q = 0; q < 4; ++q) acc[mt][nt][q] = 0.f;

    const int NKC = DIN / 32;
    for (int kc = 0; kc < NKC; ++kc) {
        const uint32_t cur = (uint32_t)(kc & 1) * BUF;
        const bool pf = (kc + 1) < NKC;
        const uint32_t nxt = (uint32_t)((kc + 1) & 1) * BUF;

        float4 f0, f1, f2, f3;
        if (pf) {
            const int ko = (kc + 1) * 32;
            CP_ASYNC16(smbase + nxt + b_h0, bhp + ko);
            CP_ASYNC16(smbase + nxt + b_h1, bhp + ko + 8);
            CP_ASYNC16(smbase + nxt + b_l0, blp + ko);
            CP_ASYNC16(smbase + nxt + b_l1, blp + ko + 8);
            CP_COMMIT();
            f0 = *(const float4*)(abase + ko);
            f1 = *(const float4*)(abase + ko + 4);
            f2 = *(const float4*)(abase + ko + 8);
            f3 = *(const float4*)(abase + ko + 12);
        }

        #pragma unroll
        for (int ks = 0; ks < 2; ++ks) {
            const uint32_t ku = (uint32_t)(2 * ks + lsel);   // 0..3
            uint32_t ah[2][4];
            #pragma unroll
            for (int mt = 0; mt < 2; ++mt) {
                int r = m0w + mt * 16 + lr;
                int blk = r >> 1, sub = r & 1;
                uint32_t addr = smbase + cur + (uint32_t)blk * 128 +
                                (((sub * 4 + ku) ^ (blk & 7)) << 4);
                ldm4(ah[mt], addr);
            }
            uint32_t bhf[4][4], blf[4][4];
            #pragma unroll
            for (int p = 0; p < 4; ++p) {
                int rn = n0w + p * 16 + lr;
                uint32_t base = smbase + cur + 8192 + (uint32_t)rn * 128;
                ldm4(bhf[p], base + (((ku    ) ^ (rn & 7)) << 4));
                ldm4(blf[p], base + (((4 + ku) ^ (rn & 7)) << 4));
            }
            // sweep 1: A*Bhi (16 independent MMAs)
            #pragma unroll
            for (int p = 0; p < 4; ++p)
                #pragma unroll
                for (int mt = 0; mt < 2; ++mt) {
                    mma16816h(acc[mt][2 * p],     ah[mt], bhf[p][0], bhf[p][2]);
                    mma16816h(acc[mt][2 * p + 1], ah[mt], bhf[p][1], bhf[p][3]);
                }
            // sweep 2: A*Blo
            #pragma unroll
            for (int p = 0; p < 4; ++p)
                #pragma unroll
                for (int mt = 0; mt < 2; ++mt) {
                    mma16816h(acc[mt][2 * p],     ah[mt], blf[p][0], blf[p][2]);
                    mma16816h(acc[mt][2 * p + 1], ah[mt], blf[p][1], blf[p][3]);
                }
        }

        if (pf) {
            *(uint4*)(sm + nxt + a_st0) = make_uint4(pack2h(f0.x, f0.y), pack2h(f0.z, f0.w),
                                                     pack2h(f1.x, f1.y), pack2h(f1.z, f1.w));
            *(uint4*)(sm + nxt + a_st1) = make_uint4(pack2h(f2.x, f2.y), pack2h(f2.z, f2.w),
                                                     pack2h(f3.x, f3.y), pack2h(f3.z, f3.w));
            CP_WAIT0();
        }
        __syncthreads();
    }

    // ---- epilogue: bias add, write g_h, fused column sum/sumsq ----
    const int erow = lane >> 2;
    const int ecol = (lane & 3) * 2;
    float* ss = (float*)sm;
    float* qq = (float*)(sm + 2048);
    #pragma unroll
    for (int nt = 0; nt < 8; ++nt) {
        int lc = n0w + nt * 8 + ecol;
        int gc = n0 + lc;
        float bx = sbias[lc], by = sbias[lc + 1];
        float sx = 0.f, sy = 0.f, qx = 0.f, qy = 0.f;
        #pragma unroll
        for (int mt = 0; mt < 2; ++mt) {
            int gr0 = row0 + m0w + mt * 16 + erow;
            float2 v0 = make_float2(acc[mt][nt][0] + bx, acc[mt][nt][1] + by);
            float2 v1 = make_float2(acc[mt][nt][2] + bx, acc[mt][nt][3] + by);
            *(float2*)&g_h[(size_t)gr0 * DHID + gc]       = v0;
            *(float2*)&g_h[(size_t)(gr0 + 8) * DHID + gc] = v1;
            sx += v0.x + v1.x;  sy += v0.y + v1.y;
            qx = fmaf(v0.x, v0.x, fmaf(v1.x, v1.x, qx));
            qy = fmaf(v0.y, v0.y, fmaf(v1.y, v1.y, qy));
        }
        #pragma unroll
        for (int o = 4; o < 32; o <<= 1) {
            sx += __shfl_xor_sync(0xffffffffu, sx, o);
            sy += __shfl_xor_sync(0xffffffffu, sy, o);
            qx += __shfl_xor_sync(0xffffffffu, qx, o);
            qy += __shfl_xor_sync(0xffffffffu, qy, o);
        }
        if (lane < 4) {
            int idx = ((wid * 8 + nt) * 4 + lane) * 2;
            ss[idx] = sx;  ss[idx + 1] = sy;
            qq[idx] = qx;  qq[idx + 1] = qy;
        }
    }
    __syncthreads();
    if (tid < 128) {
        const int lc = tid;
        const int hi = (lc >= 64);
        const int within = lc - hi * 64;
        const int nt  = within >> 3;
        const int grp = (within & 7) >> 1;
        const int xy  = within & 1;
        float s = 0.f, q = 0.f;
        #pragma unroll
        for (int w = 0; w < 4; ++w) {
            int wd = hi * 4 + w;
            int idx = ((wd * 8 + nt) * 4 + grp) * 2 + xy;
            s += ss[idx];
            q += qq[idx];
        }
        int cta = blockIdx.y * 2 + blockIdx.x;
        g_psum[cta * 128 + lc]   = s;
        g_psumsq[cta * 128 + lc] = q;
    }
}

// ---------------------------------------------------------------------------
// Kernel 3: finalize BN coefficients (256 blocks, tree reduce)
// ---------------------------------------------------------------------------
__global__ __launch_bounds__(256)
void stats_final_kernel(const float* __restrict__ gamma,
                        const float* __restrict__ beta, int nrows)
{
    __shared__ float rs[256], rq[256];
    const int c   = blockIdx.x;
    const int x   = c >> 7;
    const int lc  = c & 127;
    const int tid = threadIdx.x;
    float s = 0.f, q = 0.f;
    for (int y = tid; y < 2048; y += 256) {
        int cta = y * 2 + x;
        s += g_psum[cta * 128 + lc];
        q += g_psumsq[cta * 128 + lc];
    }
    rs[tid] = s; rq[tid] = q;
    __syncthreads();
    #pragma unroll
    for (int o = 128; o; o >>= 1) {
        if (tid < o) { rs[tid] += rs[tid + o]; rq[tid] += rq[tid + o]; }
        __syncthreads();
    }
    if (tid == 0) {
        float inv_n = 1.0f / (float)nrows;
        float mean  = rs[0] * inv_n;
        float var   = fmaf(-mean, mean, rq[0] * inv_n);
        float rstd  = rsqrtf(var + 1e-5f);
        float a     = gamma[c] * rstd;
        g_bn_a[c] = a;
        g_bn_c[c] = fmaf(-mean, a, beta[c]);
    }
}

// Kernel 4: scores (warp per row)
__global__ __launch_bounds__(256)
void scores_kernel(const float* __restrict__ W2, const float* __restrict__ b2,
                   int nrows)
{
    __shared__ float sa[DHID], sc[DHID], sw[DHID];
    const int tid = threadIdx.x;
    sa[tid] = g_bn_a[tid];
    sc[tid] = g_bn_c[tid];
    sw[tid] = W2[tid];
    __syncthreads();

    const int warp = tid >> 5;
    const int lane = tid & 31;
    const int row  = blockIdx.x * 8 + warp;
    if (row >= nrows) return;

    const float* hr = g_h + (size_t)row * DHID;
    float acc = 0.f;
    #pragma unroll
    for (int part = 0; part < 2; ++part) {
        int c0 = part * 128 + lane * 4;
        float4 v = *(const float4*)(hr + c0);
        acc += fmaxf(fmaf(sa[c0 + 0], v.x, sc[c0 + 0]), 0.f) * sw[c0 + 0];
        acc += fmaxf(fmaf(sa[c0 + 1], v.y, sc[c0 + 1]), 0.f) * sw[c0 + 1];
        acc += fmaxf(fmaf(sa[c0 + 2], v.z, sc[c0 + 2]), 0.f) * sw[c0 + 2];
        acc += fmaxf(fmaf(sa[c0 + 3], v.w, sc[c0 + 3]), 0.f) * sw[c0 + 3];
    }
    #pragma unroll
    for (int o = 16; o; o >>= 1) acc += __shfl_xor_sync(0xffffffffu, acc, o);
    if (lane == 0) g_scores[row] = acc + b2[0];
}

// Kernel 5: bag offsets
__global__ void offsets_kernel(const int* __restrict__ bag_sizes, int n_bags)
{
    if (threadIdx.x == 0 && blockIdx.x == 0) {
        long long a = 0;
        g_off[0] = 0;
        for (int b = 0; b < n_bags; ++b) { a += (long long)bag_sizes[b]; g_off[b + 1] = a; }
    }
}

// Kernel 6: per-bag stable softmax
__global__ __launch_bounds__(256)
void bag_softmax_kernel(float* __restrict__ out)
{
    __shared__ float red[256];
    const int b   = blockIdx.x;
    const int tid = threadIdx.x;
    const long long s = g_off[b];
    const long long e = g_off[b + 1];

    float m = NEG_INF_F;
    for (long long i = s + tid; i < e; i += 256) m = fmaxf(m, g_scores[i]);
    red[tid] = m;
    __syncthreads();
    #pragma unroll
    for (int o = 128; o; o >>= 1) {
        if (tid < o) red[tid] = fmaxf(red[tid], red[tid + o]);
        __syncthreads();
    }
    const float M = red[0];
    __syncthreads();

    float z = 0.f;
    for (long long i = s + tid; i < e; i += 256) {
        float ev = expf(g_scores[i] - M);
        out[i] = ev;
        z += ev;
    }
    red[tid] = z;
    __syncthreads();
    #pragma unroll
    for (int o = 128; o; o >>= 1) {
        if (tid < o) red[tid] += red[tid + o];
        __syncthreads();
    }
    const float inv = 1.0f / red[0];
    for (long long i = s + tid; i < e; i += 256) out[i] *= inv;
}

// ---------------------------------------------------------------------------
extern "C" void kernel_launch(void* const* d_in, const int* in_sizes, int n_in,
                              void* d_out, int out_size)
{
    const float* features  = (const float*)d_in[0];
    const int*   bag_sizes = (const int*)d_in[1];
    const float* W1        = (const float*)d_in[2];
    const float* b1        = (const float*)d_in[3];
    const float* gamma     = (const float*)d_in[4];
    const float* beta      = (const float*)d_in[5];
    const float* W2        = (const float*)d_in[6];
    const float* b2        = (const float*)d_in[7];
    float*       out       = (float*)d_out;

    const int n      = out_size;        // 262144
    const int n_bags = in_sizes[1];     // 128

    const int GEMM_SMEM = 49152;        // 2 x (8KB A + 16KB B)
    cudaFuncSetAttribute(gemm_mma_kernel,
                         cudaFuncAttributeMaxDynamicSharedMemorySize, GEMM_SMEM);

    convert_w1_kernel<<<DHID, 256>>>(W1);
    dim3 ggrid(2, n / 128);
    gemm_mma_kernel<<<ggrid, 256, GEMM_SMEM>>>(features, b1, n);
    stats_final_kernel<<<DHID, 256>>>(gamma, beta, n);
    scores_kernel<<<(n + 7) / 8, 256>>>(W2, b2, n);
    offsets_kernel<<<1, 1>>>(bag_sizes, n_bags);
    bag_softmax_kernel<<<n_bags, 256>>>(out);
}

// round 12
// speedup vs baseline: 1.6580x; 1.3304x over previous
#include <cuda_runtime.h>
#include <cuda_fp16.h>
#include <cstdint>

// Problem dims (fixed): N=262144 rows, d_in=1024, d_hid=256, 128 bags.
#define NROWS_MAX 262144
#define DIN 1024
#define DHID 256
#define NEG_INF_F (__int_as_float(0xff800000))

__device__ float          g_h[(size_t)NROWS_MAX * DHID];
__device__ float          g_scores[NROWS_MAX];
__device__ float          g_psum[4096 * 128];
__device__ float          g_psumsq[4096 * 128];
__device__ float          g_bn_a[DHID];
__device__ float          g_bn_c[DHID];
__device__ long long      g_off[1025];
__device__ unsigned short g_Bhi[(size_t)DHID * DIN];   // W1^T fp16 [256][1024] (K-major)

// ---------------- helpers ----------------
__device__ __forceinline__ uint32_t smem_u32(const void* p) {
    uint32_t a;
    asm("{ .reg .u64 t; cvta.to.shared.u64 t, %1; cvt.u32.u64 %0, t; }" : "=r"(a) : "l"(p));
    return a;
}
// fp16x2 pack, memory order: first, second
__device__ __forceinline__ uint32_t pack2h(float first, float second) {
    uint32_t r;
    asm("cvt.rn.f16x2.f32 %0, %1, %2;" : "=r"(r) : "f"(second), "f"(first));
    return r;
}
__device__ __forceinline__ void ldm4(uint32_t* r, uint32_t addr) {
    asm volatile("ldmatrix.sync.aligned.m8n8.x4.shared.b16 {%0,%1,%2,%3}, [%4];"
                 : "=r"(r[0]), "=r"(r[1]), "=r"(r[2]), "=r"(r[3]) : "r"(addr));
}
__device__ __forceinline__ void mma16816h(float* c, const uint32_t* a, uint32_t b0, uint32_t b1) {
    asm volatile(
        "mma.sync.aligned.m16n8k16.row.col.f32.f16.f16.f32 "
        "{%0,%1,%2,%3}, {%4,%5,%6,%7}, {%8,%9}, {%0,%1,%2,%3};"
        : "+f"(c[0]), "+f"(c[1]), "+f"(c[2]), "+f"(c[3])
        : "r"(a[0]), "r"(a[1]), "r"(a[2]), "r"(a[3]), "r"(b0), "r"(b1));
}
#define CP_ASYNC16(dst, src) \
    asm volatile("cp.async.ca.shared.global [%0], [%1], 16;" :: "r"(dst), "l"(src) : "memory")
#define CP_COMMIT()  asm volatile("cp.async.commit_group;" ::: "memory")
#define CP_WAIT0()   asm volatile("cp.async.wait_group 0;" ::: "memory")

// ---------------------------------------------------------------------------
// Kernel 0: W1 [1024][256] fp32 -> fp16 (single rounding), K-major [256][1024]
// ---------------------------------------------------------------------------
__global__ __launch_bounds__(256)
void convert_w1_kernel(const float* __restrict__ W1)
{
    const int n = blockIdx.x;
    const int t = threadIdx.x;
    #pragma unroll
    for (int i = 0; i < DIN / 256; ++i) {
        int k = t + 256 * i;
        float x = W1[(size_t)k * DHID + n];
        __half hh = __float2half_rn(x);
        g_Bhi[(size_t)n * DIN + k] = *(unsigned short*)&hh;
    }
}

// ---------------------------------------------------------------------------
// Kernel 1: single-term fp16 mma.sync GEMM  h = A_h @ B_h + b1, fused stats.
// CTA 128m x 128n (grid (2, N/128)), 256 threads, 8 warps 4m x 2n, warp 32x64.
// KC=32 double-buffered. Per-buffer: A 8KB + B 8KB, both packed 2 rows per
// 128B block (sub-row XOR swizzle, validated in R10 for A).
// Per ks: A 2 ldm4, B 4 ldm4, 16 independent MMAs (one sweep).
// ---------------------------------------------------------------------------
__global__ __launch_bounds__(256, 2)
void gemm_mma_kernel(const float* __restrict__ A, const float* __restrict__ b1, int nrows)
{
    extern __shared__ __align__(16) char sm[];
    __shared__ float sbias[128];

    const int tid  = threadIdx.x;
    const int wid  = tid >> 5;
    const int lane = tid & 31;
    const int n0   = blockIdx.x * 128;
    const int row0 = blockIdx.y * 128;

    const uint32_t smbase = smem_u32(sm);
    const int BUF = 16384;   // per-buffer: A 8KB @ +0, B 8KB @ +8192

    if (tid < 128) sbias[tid] = b1[n0 + tid];

    // ---- A staging map: row = tid>>1, cols (tid&1)*16..+15 (fp32) ----
    const int arow = tid >> 1;
    const int asub = arow & 1;
    const int ablk = arow >> 1;
    const int ku0  = (tid & 1) * 2;          // 16B units within row: ku0, ku0+1
    const float* abase = A + (size_t)(row0 + arow) * DIN + (tid & 1) * 16;
    const uint32_t a_st0 = (uint32_t)ablk * 128 + (((asub * 4 + ku0    ) ^ (ablk & 7)) << 4);
    const uint32_t a_st1 = (uint32_t)ablk * 128 + (((asub * 4 + ku0 + 1) ^ (ablk & 7)) << 4);

    // ---- B staging map: row = tid>>1, units kh*2+{0,1} (fp16, cp.async) ----
    const int bn  = tid >> 1;
    const int kh  = tid & 1;
    const int bsub = bn & 1;
    const int bblk = bn >> 1;
    const unsigned short* bhp = g_Bhi + (size_t)(n0 + bn) * DIN + kh * 16;
    const uint32_t b_s0 = 8192u + (uint32_t)bblk * 128 +
                          (((bsub * 4 + kh * 2    ) ^ (bblk & 7)) << 4);
    const uint32_t b_s1 = 8192u + (uint32_t)bblk * 128 +
                          (((bsub * 4 + kh * 2 + 1) ^ (bblk & 7)) << 4);

    // ---- stage chunk 0 ----
    {
        CP_ASYNC16(smbase + b_s0, bhp);
        CP_ASYNC16(smbase + b_s1, bhp + 8);
        CP_COMMIT();
        float4 f0 = *(const float4*)(abase);
        float4 f1 = *(const float4*)(abase + 4);
        float4 f2 = *(const float4*)(abase + 8);
        float4 f3 = *(const float4*)(abase + 12);
        *(uint4*)(sm + a_st0) = make_uint4(pack2h(f0.x, f0.y), pack2h(f0.z, f0.w),
                                           pack2h(f1.x, f1.y), pack2h(f1.z, f1.w));
        *(uint4*)(sm + a_st1) = make_uint4(pack2h(f2.x, f2.y), pack2h(f2.z, f2.w),
                                           pack2h(f3.x, f3.y), pack2h(f3.z, f3.w));
        CP_WAIT0();
    }
    __syncthreads();

    const int m0w  = (wid & 3) * 32;
    const int n0w  = (wid >> 2) * 64;
    const int lr   = lane & 15;
    const int lsel = (lane >> 4) & 1;

    float acc[2][8][4];
    #pragma unroll
    for (int mt = 0; mt < 2; ++mt)
        #pragma unroll
        for (int nt = 0; nt < 8; ++nt)
            #pragma unroll
            for (int q = 0; q < 4; ++q) acc[mt][nt][q] = 0.f;

    const int NKC = DIN / 32;
    for (int kc = 0; kc < NKC; ++kc) {
        const uint32_t cur = (uint32_t)(kc & 1) * BUF;
        const bool pf = (kc + 1) < NKC;
        const uint32_t nxt = (uint32_t)((kc + 1) & 1) * BUF;

        float4 f0, f1, f2, f3;
        if (pf) {
            const int ko = (kc + 1) * 32;
            CP_ASYNC16(smbase + nxt + b_s0, bhp + ko);
            CP_ASYNC16(smbase + nxt + b_s1, bhp + ko + 8);
            CP_COMMIT();
            f0 = *(const float4*)(abase + ko);
            f1 = *(const float4*)(abase + ko + 4);
            f2 = *(const float4*)(abase + ko + 8);
            f3 = *(const float4*)(abase + ko + 12);
        }

        #pragma unroll
        for (int ks = 0; ks < 2; ++ks) {
            const uint32_t ku = (uint32_t)(2 * ks + lsel);   // 0..3
            uint32_t ah[2][4];
            #pragma unroll
            for (int mt = 0; mt < 2; ++mt) {
                int r = m0w + mt * 16 + lr;
                int blk = r >> 1, sub = r & 1;
                uint32_t addr = smbase + cur + (uint32_t)blk * 128 +
                                (((sub * 4 + ku) ^ (blk & 7)) << 4);
                ldm4(ah[mt], addr);
            }
            uint32_t bhf[4][4];
            #pragma unroll
            for (int p = 0; p < 4; ++p) {
                int rn = n0w + p * 16 + lr;
                int blk = rn >> 1, sub = rn & 1;
                uint32_t addr = smbase + cur + 8192 + (uint32_t)blk * 128 +
                                (((sub * 4 + ku) ^ (blk & 7)) << 4);
                ldm4(bhf[p], addr);
            }
            // single sweep: 16 independent MMAs
            #pragma unroll
            for (int p = 0; p < 4; ++p)
                #pragma unroll
                for (int mt = 0; mt < 2; ++mt) {
                    mma16816h(acc[mt][2 * p],     ah[mt], bhf[p][0], bhf[p][2]);
                    mma16816h(acc[mt][2 * p + 1], ah[mt], bhf[p][1], bhf[p][3]);
                }
        }

        if (pf) {
            *(uint4*)(sm + nxt + a_st0) = make_uint4(pack2h(f0.x, f0.y), pack2h(f0.z, f0.w),
                                                     pack2h(f1.x, f1.y), pack2h(f1.z, f1.w));
            *(uint4*)(sm + nxt + a_st1) = make_uint4(pack2h(f2.x, f2.y), pack2h(f2.z, f2.w),
                                                     pack2h(f3.x, f3.y), pack2h(f3.z, f3.w));
            CP_WAIT0();
        }
        __syncthreads();
    }

    // ---- epilogue: bias add, write g_h, fused column sum/sumsq ----
    const int erow = lane >> 2;
    const int ecol = (lane & 3) * 2;
    float* ss = (float*)sm;
    float* qq = (float*)(sm + 2048);
    #pragma unroll
    for (int nt = 0; nt < 8; ++nt) {
        int lc = n0w + nt * 8 + ecol;
        int gc = n0 + lc;
        float bx = sbias[lc], by = sbias[lc + 1];
        float sx = 0.f, sy = 0.f, qx = 0.f, qy = 0.f;
        #pragma unroll
        for (int mt = 0; mt < 2; ++mt) {
            int gr0 = row0 + m0w + mt * 16 + erow;
            float2 v0 = make_float2(acc[mt][nt][0] + bx, acc[mt][nt][1] + by);
            float2 v1 = make_float2(acc[mt][nt][2] + bx, acc[mt][nt][3] + by);
            *(float2*)&g_h[(size_t)gr0 * DHID + gc]       = v0;
            *(float2*)&g_h[(size_t)(gr0 + 8) * DHID + gc] = v1;
            sx += v0.x + v1.x;  sy += v0.y + v1.y;
            qx = fmaf(v0.x, v0.x, fmaf(v1.x, v1.x, qx));
            qy = fmaf(v0.y, v0.y, fmaf(v1.y, v1.y, qy));
        }
        #pragma unroll
        for (int o = 4; o < 32; o <<= 1) {
            sx += __shfl_xor_sync(0xffffffffu, sx, o);
            sy += __shfl_xor_sync(0xffffffffu, sy, o);
            qx += __shfl_xor_sync(0xffffffffu, qx, o);
            qy += __shfl_xor_sync(0xffffffffu, qy, o);
        }
        if (lane < 4) {
            int idx = ((wid * 8 + nt) * 4 + lane) * 2;
            ss[idx] = sx;  ss[idx + 1] = sy;
            qq[idx] = qx;  qq[idx + 1] = qy;
        }
    }
    __syncthreads();
    if (tid < 128) {
        const int lc = tid;
        const int hi = (lc >= 64);
        const int within = lc - hi * 64;
        const int nt  = within >> 3;
        const int grp = (within & 7) >> 1;
        const int xy  = within & 1;
        float s = 0.f, q = 0.f;
        #pragma unroll
        for (int w = 0; w < 4; ++w) {
            int wd = hi * 4 + w;
            int idx = ((wd * 8 + nt) * 4 + grp) * 2 + xy;
            s += ss[idx];
            q += qq[idx];
        }
        int cta = blockIdx.y * 2 + blockIdx.x;
        g_psum[cta * 128 + lc]   = s;
        g_psumsq[cta * 128 + lc] = q;
    }
}

// ---------------------------------------------------------------------------
// Kernel 3: finalize BN coefficients (256 blocks, tree reduce)
// ---------------------------------------------------------------------------
__global__ __launch_bounds__(256)
void stats_final_kernel(const float* __restrict__ gamma,
                        const float* __restrict__ beta, int nrows)
{
    __shared__ float rs[256], rq[256];
    const int c   = blockIdx.x;
    const int x   = c >> 7;
    const int lc  = c & 127;
    const int tid = threadIdx.x;
    float s = 0.f, q = 0.f;
    for (int y = tid; y < 2048; y += 256) {
        int cta = y * 2 + x;
        s += g_psum[cta * 128 + lc];
        q += g_psumsq[cta * 128 + lc];
    }
    rs[tid] = s; rq[tid] = q;
    __syncthreads();
    #pragma unroll
    for (int o = 128; o; o >>= 1) {
        if (tid < o) { rs[tid] += rs[tid + o]; rq[tid] += rq[tid + o]; }
        __syncthreads();
    }
    if (tid == 0) {
        float inv_n = 1.0f / (float)nrows;
        float mean  = rs[0] * inv_n;
        float var   = fmaf(-mean, mean, rq[0] * inv_n);
        float rstd  = rsqrtf(var + 1e-5f);
        float a     = gamma[c] * rstd;
        g_bn_a[c] = a;
        g_bn_c[c] = fmaf(-mean, a, beta[c]);
    }
}

// Kernel 4: scores (warp per row)
__global__ __launch_bounds__(256)
void scores_kernel(const float* __restrict__ W2, const float* __restrict__ b2,
                   int nrows)
{
    __shared__ float sa[DHID], sc[DHID], sw[DHID];
    const int tid = threadIdx.x;
    sa[tid] = g_bn_a[tid];
    sc[tid] = g_bn_c[tid];
    sw[tid] = W2[tid];
    __syncthreads();

    const int warp = tid >> 5;
    const int lane = tid & 31;
    const int row  = blockIdx.x * 8 + warp;
    if (row >= nrows) return;

    const float* hr = g_h + (size_t)row * DHID;
    float acc = 0.f;
    #pragma unroll
    for (int part = 0; part < 2; ++part) {
        int c0 = part * 128 + lane * 4;
        float4 v = *(const float4*)(hr + c0);
        acc += fmaxf(fmaf(sa[c0 + 0], v.x, sc[c0 + 0]), 0.f) * sw[c0 + 0];
        acc += fmaxf(fmaf(sa[c0 + 1], v.y, sc[c0 + 1]), 0.f) * sw[c0 + 1];
        acc += fmaxf(fmaf(sa[c0 + 2], v.z, sc[c0 + 2]), 0.f) * sw[c0 + 2];
        acc += fmaxf(fmaf(sa[c0 + 3], v.w, sc[c0 + 3]), 0.f) * sw[c0 + 3];
    }
    #pragma unroll
    for (int o = 16; o; o >>= 1) acc += __shfl_xor_sync(0xffffffffu, acc, o);
    if (lane == 0) g_scores[row] = acc + b2[0];
}

// Kernel 5: bag offsets
__global__ void offsets_kernel(const int* __restrict__ bag_sizes, int n_bags)
{
    if (threadIdx.x == 0 && blockIdx.x == 0) {
        long long a = 0;
        g_off[0] = 0;
        for (int b = 0; b < n_bags; ++b) { a += (long long)bag_sizes[b]; g_off[b + 1] = a; }
    }
}

// Kernel 6: per-bag stable softmax
__global__ __launch_bounds__(256)
void bag_softmax_kernel(float* __restrict__ out)
{
    __shared__ float red[256];
    const int b   = blockIdx.x;
    const int tid = threadIdx.x;
    const long long s = g_off[b];
    const long long e = g_off[b + 1];

    float m = NEG_INF_F;
    for (long long i = s + tid; i < e; i += 256) m = fmaxf(m, g_scores[i]);
    red[tid] = m;
    __syncthreads();
    #pragma unroll
    for (int o = 128; o; o >>= 1) {
        if (tid < o) red[tid] = fmaxf(red[tid], red[tid + o]);
        __syncthreads();
    }
    const float M = red[0];
    __syncthreads();

    float z = 0.f;
    for (long long i = s + tid; i < e; i += 256) {
        float ev = expf(g_scores[i] - M);
        out[i] = ev;
        z += ev;
    }
    red[tid] = z;
    __syncthreads();
    #pragma unroll
    for (int o = 128; o; o >>= 1) {
        if (tid < o) red[tid] += red[tid + o];
        __syncthreads();
    }
    const float inv = 1.0f / red[0];
    for (long long i = s + tid; i < e; i += 256) out[i] *= inv;
}

// ---------------------------------------------------------------------------
extern "C" void kernel_launch(void* const* d_in, const int* in_sizes, int n_in,
                              void* d_out, int out_size)
{
    const float* features  = (const float*)d_in[0];
    const int*   bag_sizes = (const int*)d_in[1];
    const float* W1        = (const float*)d_in[2];
    const float* b1        = (const float*)d_in[3];
    const float* gamma     = (const float*)d_in[4];
    const float* beta      = (const float*)d_in[5];
    const float* W2        = (const float*)d_in[6];
    const float* b2        = (const float*)d_in[7];
    float*       out       = (float*)d_out;

    const int n      = out_size;        // 262144
    const int n_bags = in_sizes[1];     // 128

    const int GEMM_SMEM = 32768;        // 2 x (8KB A + 8KB B)
    cudaFuncSetAttribute(gemm_mma_kernel,
                         cudaFuncAttributeMaxDynamicSharedMemorySize, GEMM_SMEM);

    convert_w1_kernel<<<DHID, 256>>>(W1);
    dim3 ggrid(2, n / 128);
    gemm_mma_kernel<<<ggrid, 256, GEMM_SMEM>>>(features, b1, n);
    stats_final_kernel<<<DHID, 256>>>(gamma, beta, n);
    scores_kernel<<<(n + 7) / 8, 256>>>(W2, b2, n);
    offsets_kernel<<<1, 1>>>(bag_sizes, n_bags);
    bag_softmax_kernel<<<n_bags, 256>>>(out);
}